// round 6
// baseline (speedup 1.0000x reference)
#include <cuda_runtime.h>
#include <cstdint>

#define BB   2048
#define TTd  200
#define FSZ  128
#define H1N  80
#define H2N  40
#define KC   32
#define NCH  4
#define SFP  205            // t-stride: 4*205 mod 32 = 20 -> conflict-free transpose stores
#define NEG_BIG_F (-4294967295.0f)

// ---- shared memory float offsets for k_scores ----
#define OF_SF    0                       // 2*32*205 = 13120 (also GEMM2 partial scratch)
#define OF_SMT   13120                   // 128*80   = 10240
#define OF_SH1T  23360                   // 80*205   = 16400 (H1 transposed [k][t])
#define OF_SW2   39760                   // 80*40    = 3200  ([k][h2])
#define OF_SPART 42960                   // 10*200   = 2000
#define OF_SQ    44960                   // 128
#define OF_SCB   45088                   // 80
#define OF_RED   45168                   // 32
#define SMEM_FLOATS 45200                // *4 = 180,800 bytes

// ---- device scratch (static, no runtime allocation) ----
__device__ float g_q  [BB * FSZ];
__device__ float g_cb [BB * H1N];
__device__ float g_AT [FSZ * H1N];
__device__ float g_BmT[FSZ * H1N];
__device__ float g_C2T[FSZ * H1N];
__device__ float g_WqT[FSZ * FSZ];
__device__ int   g_maskI32;

// packed fp32x2 helpers (Blackwell paired FP32 — 2x scalar FFMA throughput)
__device__ __forceinline__ void fma2(unsigned long long &d,
                                     unsigned long long a,
                                     unsigned long long b) {
    asm("fma.rn.f32x2 %0, %1, %2, %0;" : "+l"(d) : "l"(a), "l"(b));
}
__device__ __forceinline__ unsigned long long dup2(float x) {
    unsigned long long r;
    asm("mov.b64 %0, {%1, %1};" : "=l"(r) : "f"(x));
    return r;
}
__device__ __forceinline__ float sigf(float x) {
    return 1.0f / (1.0f + __expf(-x));
}

// ============================================================
// Kernel 0: mask dtype probe (JAX bool as int32 vs byte mask).
// ============================================================
__global__ void k_detect(const unsigned char* __restrict__ m) {
    __shared__ int bad;
    if (threadIdx.x == 0) bad = 0;
    __syncthreads();
    int acc = 0;
    for (int i = threadIdx.x; i < 4096; i += blockDim.x)
        if ((i & 3) && m[i]) acc = 1;
    if (acc) atomicOr(&bad, 1);
    __syncthreads();
    if (threadIdx.x == 0) g_maskI32 = bad ? 0 : 1;
}

// ============================================================
// Kernel 1: weight preprocessing (DIN concat factorization).
// ============================================================
__global__ void k_prep(const float* __restrict__ W1, const float* __restrict__ Wq) {
    int idx = blockIdx.x * blockDim.x + threadIdx.x;
    if (idx < FSZ * H1N) {
        int d = idx / H1N, h = idx - d * H1N;
        const float* r = W1 + (size_t)h * 4 * FSZ;
        float w0 = r[d], w1 = r[FSZ + d], w2 = r[2 * FSZ + d], w3v = r[3 * FSZ + d];
        g_AT[idx]  = w0 + w2;
        g_BmT[idx] = w1 - w2;
        g_C2T[idx] = w3v;
    }
    if (idx < FSZ * FSZ) {
        int k = idx / FSZ, d = idx - k * FSZ;
        g_WqT[idx] = Wq[d * FSZ + k];
    }
}

// ============================================================
// Kernel 2: q = PReLU(query @ Wq^T + bq), c_b = q @ A^T + b1
// ============================================================
__global__ void k_query(const float* __restrict__ query, const float* __restrict__ bq,
                        const float* __restrict__ aP, const float* __restrict__ b1) {
    __shared__ float sqr[FSZ];
    __shared__ float sqv[FSZ];
    int b = blockIdx.x, tid = threadIdx.x;
    sqr[tid] = query[(size_t)b * FSZ + tid];
    __syncthreads();
    float acc = 0.f;
#pragma unroll 8
    for (int k = 0; k < FSZ; k++) acc += sqr[k] * g_WqT[k * FSZ + tid];
    acc += bq[tid];
    float a = aP[0];
    float q = acc > 0.f ? acc : a * acc;
    g_q[(size_t)b * FSZ + tid] = q;
    sqv[tid] = q;
    __syncthreads();
    if (tid < H1N) {
        float c = 0.f;
#pragma unroll 8
        for (int d = 0; d < FSZ; d++) c += sqv[d] * g_AT[d * H1N + tid];
        g_cb[(size_t)b * H1N + tid] = c + b1[tid];
    }
}

// ============================================================
// Kernel 3: one CTA per batch, 512 threads, K-SPLIT into 2 groups.
//   kg = tid/256; id = tid%256; active = id<250.
//   rt = id%25 -> t = rt + 25*i (i<8, strided tile, contiguous lane loads)
//   ch = id/25 -> h-cols ch*8.. (near-warp-uniform -> broadcast m loads)
// GEMM1 (k-split within each 32-k chunk: kg0 kk 0-15, kg1 16-31)
// -> smem combine + sigmoid -> H1 transposed [k][t]
// GEMM2 (kg0 k 0-39, kg1 40-79) -> combine + sigmoid + W3 dot
// -> masked softmax -> fused facts*score.
// ============================================================
__global__ __launch_bounds__(512, 1)
void k_scores(const float* __restrict__ facts, const unsigned char* __restrict__ mask,
              const float* __restrict__ W2, const float* __restrict__ b2,
              const float* __restrict__ W3, const float* __restrict__ b3,
              float* __restrict__ out, float* __restrict__ scoresOut) {
    extern __shared__ float sm[];
    float* sF    = sm + OF_SF;     // [2][32][SFP] transposed facts chunks
    float* sMt   = sm + OF_SMT;    // [128][80]   per-batch effective W1
    float* sH1T  = sm + OF_SH1T;   // [80][SFP]   H1 transposed
    float* sW2t  = sm + OF_SW2;    // [80][40]    W2 transposed [k][h2]
    float* sPart = sm + OF_SPART;  // [10][200]
    float* sq    = sm + OF_SQ;
    float* scb   = sm + OF_SCB;
    float* red   = sm + OF_RED;

    int b = blockIdx.x, tid = threadIdx.x;
    int kg = tid >> 8;           // k-group 0/1
    int id = tid & 255;
    bool active = id < 250;
    int rt = id % 25;            // t = rt + 25*i
    int ch = id / 25;            // 0..9

    // -------- prelude --------
    if (tid < FSZ) sq[tid]  = g_q[(size_t)b * FSZ + tid];
    if (tid < H1N) scb[tid] = g_cb[(size_t)b * H1N + tid];
    for (int i = tid; i < H2N * H1N; i += 512) {       // W2t[k][h2] = W2[h2][k]
        int h2 = i / H1N, k = i - h2 * H1N;
        sW2t[k * H2N + h2] = W2[i];
    }
    __syncthreads();

    const float4* factsB = (const float4*)(facts + (size_t)b * TTd * FSZ);

    // chunk 0 global loads + M_b build, then transpose-store chunk 0
    float4 pf[4];
#pragma unroll
    for (int r = 0; r < 4; r++) {
        int i = tid + r * 512;
        if (i < 1600) { int t = i >> 3, j = i & 7; pf[r] = factsB[t * 32 + j]; }
    }
    for (int i = tid; i < FSZ * H1N; i += 512)
        sMt[i] = g_BmT[i] + sq[i / H1N] * g_C2T[i];
#pragma unroll
    for (int r = 0; r < 4; r++) {
        int i = tid + r * 512;
        if (i < 1600) {
            int t = i >> 3, j = i & 7;
            float* p = sF + (j * 4) * SFP + t;
            p[0] = pf[r].x; p[SFP] = pf[r].y; p[2 * SFP] = pf[r].z; p[3 * SFP] = pf[r].w;
        }
    }
    __syncthreads();

    // -------- GEMM1: acc[8 t][4 h-pairs], packed f32x2, k-split --------
    unsigned long long acc[8][4];
#pragma unroll
    for (int i = 0; i < 8; i++)
#pragma unroll
        for (int j = 0; j < 4; j++) acc[i][j] = 0ull;

    for (int c = 0; c < NCH; c++) {
        const float* sFb = sF + (c & 1) * (KC * SFP);
        if (c < NCH - 1) {
#pragma unroll
            for (int r = 0; r < 4; r++) {
                int i = tid + r * 512;
                if (i < 1600) { int t = i >> 3, j = i & 7; pf[r] = factsB[t * 32 + (c + 1) * 8 + j]; }
            }
        }
        if (active) {
#pragma unroll 2
            for (int s = 0; s < 16; s++) {
                int kkl  = kg * 16 + s;               // sF row within chunk
                int krow = c * KC + kkl;              // sMt row
                const float* fb = sFb + kkl * SFP + rt;
                float f[8];
#pragma unroll
                for (int i = 0; i < 8; i++) f[i] = fb[25 * i];
                const ulonglong2* mp = (const ulonglong2*)(sMt + krow * H1N + ch * 8);
                ulonglong2 mA = mp[0], mB = mp[1];
#pragma unroll
                for (int i = 0; i < 8; i++) {
                    unsigned long long a_ = dup2(f[i]);
                    fma2(acc[i][0], a_, mA.x); fma2(acc[i][1], a_, mA.y);
                    fma2(acc[i][2], a_, mB.x); fma2(acc[i][3], a_, mB.y);
                }
            }
        }
        if (c < NCH - 1) {
#pragma unroll
            for (int r = 0; r < 4; r++) {
                int i = tid + r * 512;
                if (i < 1600) {
                    int t = i >> 3, j = i & 7;
                    float* p = sF + ((c + 1) & 1) * (KC * SFP) + (j * 4) * SFP + t;
                    p[0] = pf[r].x; p[SFP] = pf[r].y; p[2 * SFP] = pf[r].z; p[3 * SFP] = pf[r].w;
                }
            }
        }
        __syncthreads();
    }

    // -------- GEMM1 combine: kg0 stores partials, kg1 adds + sigmoid --------
    if (active && kg == 0) {
#pragma unroll
        for (int i = 0; i < 8; i++) {
            int t = rt + 25 * i;
#pragma unroll
            for (int j = 0; j < 4; j++) {
                float2 v = *(float2*)&acc[i][j];
                int h = ch * 8 + 2 * j;
                sH1T[h * SFP + t] = v.x;
                sH1T[(h + 1) * SFP + t] = v.y;
            }
        }
    }
    __syncthreads();
    if (active && kg == 1) {
#pragma unroll
        for (int i = 0; i < 8; i++) {
            int t = rt + 25 * i;
#pragma unroll
            for (int j = 0; j < 4; j++) {
                float2 v = *(float2*)&acc[i][j];
                int h = ch * 8 + 2 * j;
                sH1T[h * SFP + t]       = sigf(v.x + sH1T[h * SFP + t] + scb[h]);
                sH1T[(h + 1) * SFP + t] = sigf(v.y + sH1T[(h + 1) * SFP + t] + scb[h + 1]);
            }
        }
    }
    __syncthreads();

    // -------- GEMM2: acc2[8 t][2 h2-pairs], k-split (kg0: 0-39, kg1: 40-79) --------
    unsigned long long acc2[8][2];
#pragma unroll
    for (int i = 0; i < 8; i++) { acc2[i][0] = 0ull; acc2[i][1] = 0ull; }
    if (active) {
#pragma unroll 4
        for (int k0 = 0; k0 < 40; k0++) {
            int k = kg * 40 + k0;
            const float* hb = sH1T + k * SFP + rt;
            float h1[8];
#pragma unroll
            for (int i = 0; i < 8; i++) h1[i] = hb[25 * i];
            ulonglong2 w2v = *(const ulonglong2*)(sW2t + k * H2N + ch * 4);
#pragma unroll
            for (int i = 0; i < 8; i++) {
                unsigned long long a_ = dup2(h1[i]);
                fma2(acc2[i][0], a_, w2v.x);
                fma2(acc2[i][1], a_, w2v.y);
            }
        }
    }
    // combine: kg0 stores partials into sF scratch, kg1 finishes + W3 dot
    float* sG = sF;   // free after GEMM1; 40 rows x SFP
    if (active && kg == 0) {
#pragma unroll
        for (int i = 0; i < 8; i++) {
            int t = rt + 25 * i;
            float2 v0 = *(float2*)&acc2[i][0];
            float2 v1 = *(float2*)&acc2[i][1];
            int h2 = ch * 4;
            sG[h2 * SFP + t] = v0.x;
            sG[(h2 + 1) * SFP + t] = v0.y;
            sG[(h2 + 2) * SFP + t] = v1.x;
            sG[(h2 + 3) * SFP + t] = v1.y;
        }
    }
    __syncthreads();
    if (active && kg == 1) {
        float b2r[4], w3r[4];
#pragma unroll
        for (int jj = 0; jj < 4; jj++) { b2r[jj] = b2[ch * 4 + jj]; w3r[jj] = W3[ch * 4 + jj]; }
#pragma unroll
        for (int i = 0; i < 8; i++) {
            int t = rt + 25 * i;
            float2 v0 = *(float2*)&acc2[i][0];
            float2 v1 = *(float2*)&acc2[i][1];
            int h2 = ch * 4;
            float part = sigf(v0.x + sG[h2 * SFP + t]       + b2r[0]) * w3r[0]
                       + sigf(v0.y + sG[(h2 + 1) * SFP + t] + b2r[1]) * w3r[1]
                       + sigf(v1.x + sG[(h2 + 2) * SFP + t] + b2r[2]) * w3r[2]
                       + sigf(v1.y + sG[(h2 + 3) * SFP + t] + b2r[3]) * w3r[3];
            sPart[ch * TTd + t] = part;
        }
    }
    __syncthreads();

    // -------- stage 3 reduce + masked softmax over T=200 (16 warps) --------
    int lane = tid & 31, wid = tid >> 5;
    float sval = 0.f, mpad = -3.402823466e38f;
    if (tid < TTd) {
        float s = b3[0];
#pragma unroll
        for (int c2 = 0; c2 < 10; c2++) s += sPart[c2 * TTd + tid];
        int mv;
        if (g_maskI32) mv = ((const int*)mask)[(size_t)b * TTd + tid];
        else           mv = (int)mask[(size_t)b * TTd + tid];
        if (!mv) s = NEG_BIG_F;
        sval = s; mpad = s;
    }
    float m = mpad;
#pragma unroll
    for (int o = 16; o; o >>= 1) m = fmaxf(m, __shfl_xor_sync(0xffffffffu, m, o));
    if (lane == 0) red[wid] = m;
    __syncthreads();
    if (tid < 32) {
        float mm = (tid < 16) ? red[tid] : -3.402823466e38f;
#pragma unroll
        for (int o = 8; o; o >>= 1) mm = fmaxf(mm, __shfl_xor_sync(0xffffffffu, mm, o));
        if (tid == 0) red[0] = mm;
    }
    __syncthreads();
    float bmax = red[0];
    float p = (tid < TTd) ? __expf(sval - bmax) : 0.f;
    float ssum = p;
#pragma unroll
    for (int o = 16; o; o >>= 1) ssum += __shfl_xor_sync(0xffffffffu, ssum, o);
    __syncthreads();
    if (lane == 0) red[wid] = ssum;
    __syncthreads();
    if (tid < 32) {
        float ss = (tid < 16) ? red[tid] : 0.f;
#pragma unroll
        for (int o = 8; o; o >>= 1) ss += __shfl_xor_sync(0xffffffffu, ss, o);
        if (tid == 0) red[0] = ss;
    }
    __syncthreads();
    float tot = red[0];
    float* sc = sPart;                       // reuse
    if (tid < TTd) {
        float v = p / tot;
        sc[tid] = v;
        scoresOut[(size_t)b * TTd + tid] = v;
    }
    __syncthreads();

    // -------- fused output scaling: out[b,t,:] = facts[b,t,:] * score --------
    float4* out4 = (float4*)(out + (size_t)b * TTd * FSZ);
#pragma unroll 4
    for (int i = tid; i < TTd * (FSZ / 4); i += 512) {
        float s = sc[i >> 5];
        float4 f = factsB[i];
        out4[i] = make_float4(f.x * s, f.y * s, f.z * s, f.w * s);
    }
}

extern "C" void kernel_launch(void* const* d_in, const int* in_sizes, int n_in,
                              void* d_out, int out_size) {
    const float*         query = (const float*)d_in[0];
    const float*         facts = (const float*)d_in[1];
    const unsigned char* maskp = (const unsigned char*)d_in[2];
    const float*         Wq    = (const float*)d_in[3];
    const float*         bq    = (const float*)d_in[4];
    const float*         aP    = (const float*)d_in[5];
    const float*         W1    = (const float*)d_in[6];
    const float*         b1    = (const float*)d_in[7];
    const float*         W2    = (const float*)d_in[8];
    const float*         b2    = (const float*)d_in[9];
    const float*         W3    = (const float*)d_in[10];
    const float*         b3    = (const float*)d_in[11];

    float* out       = (float*)d_out;
    float* scoresOut = out + (size_t)BB * TTd * FSZ;

    cudaFuncSetAttribute(k_scores, cudaFuncAttributeMaxDynamicSharedMemorySize,
                         SMEM_FLOATS * 4);

    k_detect<<<1, 256>>>(maskp);
    k_prep <<<64, 256>>>(W1, Wq);
    k_query<<<BB, 128>>>(query, bq, aP, b1);
    k_scores<<<BB, 512, SMEM_FLOATS * 4>>>(facts, maskp, W2, b2, W3, b3, out, scoresOut);
}

// round 7
// speedup vs baseline: 1.0590x; 1.0590x over previous
#include <cuda_runtime.h>
#include <cstdint>

#define BB   2048
#define TTd  200
#define FSZ  128
#define H1N  80
#define H2N  40
#define KC   32
#define NCH  4
#define SFP  205            // t-stride: conflict-free transpose stores & strided loads
#define NEG_BIG_F (-4294967295.0f)

// ---- shared memory float offsets for k_scores ----
#define OF_SF    0                       // 2*32*205 = 13120
#define OF_SMT   13120                   // 128*80   = 10240
#define OF_SH1T  23360                   // 80*205   = 16400 (H1 transposed [k][t])
#define OF_SW2   39760                   // 80*40    = 3200  ([k][h2])
#define OF_SPART 42960                   // 10*200   = 2000
#define OF_SQ    44960                   // 128
#define OF_SCB   45088                   // 80
#define OF_RED   45168                   // 32
#define SMEM_FLOATS 45200                // *4 = 180,800 bytes

// ---- device scratch (static, no runtime allocation) ----
__device__ float g_q  [BB * FSZ];
__device__ float g_cb [BB * H1N];
__device__ float g_AT [FSZ * H1N];
__device__ float g_BmT[FSZ * H1N];
__device__ float g_C2T[FSZ * H1N];
__device__ float g_WqT[FSZ * FSZ];
__device__ int   g_maskI32;

// packed fp32x2 helpers (Blackwell paired FP32 — 2x scalar FFMA throughput)
__device__ __forceinline__ void fma2(unsigned long long &d,
                                     unsigned long long a,
                                     unsigned long long b) {
    asm("fma.rn.f32x2 %0, %1, %2, %0;" : "+l"(d) : "l"(a), "l"(b));
}
__device__ __forceinline__ unsigned long long dup2(float x) {
    unsigned long long r;
    asm("mov.b64 %0, {%1, %1};" : "=l"(r) : "f"(x));
    return r;
}
__device__ __forceinline__ float sigf(float x) {
    return 1.0f / (1.0f + __expf(-x));
}

// ============================================================
// Kernel 0: mask dtype probe (JAX bool as int32 vs byte mask).
// ============================================================
__global__ void k_detect(const unsigned char* __restrict__ m) {
    __shared__ int bad;
    if (threadIdx.x == 0) bad = 0;
    __syncthreads();
    int acc = 0;
    for (int i = threadIdx.x; i < 4096; i += blockDim.x)
        if ((i & 3) && m[i]) acc = 1;
    if (acc) atomicOr(&bad, 1);
    __syncthreads();
    if (threadIdx.x == 0) g_maskI32 = bad ? 0 : 1;
}

// ============================================================
// Kernel 1: weight preprocessing (DIN concat factorization).
// ============================================================
__global__ void k_prep(const float* __restrict__ W1, const float* __restrict__ Wq) {
    int idx = blockIdx.x * blockDim.x + threadIdx.x;
    if (idx < FSZ * H1N) {
        int d = idx / H1N, h = idx - d * H1N;
        const float* r = W1 + (size_t)h * 4 * FSZ;
        float w0 = r[d], w1 = r[FSZ + d], w2 = r[2 * FSZ + d], w3v = r[3 * FSZ + d];
        g_AT[idx]  = w0 + w2;
        g_BmT[idx] = w1 - w2;
        g_C2T[idx] = w3v;
    }
    if (idx < FSZ * FSZ) {
        int k = idx / FSZ, d = idx - k * FSZ;
        g_WqT[idx] = Wq[d * FSZ + k];
    }
}

// ============================================================
// Kernel 2: q = PReLU(query @ Wq^T + bq), c_b = q @ A^T + b1
// ============================================================
__global__ void k_query(const float* __restrict__ query, const float* __restrict__ bq,
                        const float* __restrict__ aP, const float* __restrict__ b1) {
    __shared__ float sqr[FSZ];
    __shared__ float sqv[FSZ];
    int b = blockIdx.x, tid = threadIdx.x;
    sqr[tid] = query[(size_t)b * FSZ + tid];
    __syncthreads();
    float acc = 0.f;
#pragma unroll 8
    for (int k = 0; k < FSZ; k++) acc += sqr[k] * g_WqT[k * FSZ + tid];
    acc += bq[tid];
    float a = aP[0];
    float q = acc > 0.f ? acc : a * acc;
    g_q[(size_t)b * FSZ + tid] = q;
    sqv[tid] = q;
    __syncthreads();
    if (tid < H1N) {
        float c = 0.f;
#pragma unroll 8
        for (int d = 0; d < FSZ; d++) c += sqv[d] * g_AT[d * H1N + tid];
        g_cb[(size_t)b * H1N + tid] = c + b1[tid];
    }
}

// ============================================================
// Kernel 3: one CTA per batch, 512 threads (500 active in GEMM).
//   rt = tid%50 -> t = rt + 50*i (i<4, lane-contiguous loads)
//   ch = tid/50 -> h-cols ch*8 (near-warp-uniform m loads)
// Manual register double-buffering in both GEMM mainloops to kill
// LDS->FFMA RAW stalls (R6 was scoreboard-stall bound: issue 34%).
// GEMM1 -> sigmoid -> H1T[k][t] -> GEMM2 -> sigmoid + W3 dot
// -> masked softmax -> fused facts*score.
// ============================================================
__global__ __launch_bounds__(512, 1)
void k_scores(const float* __restrict__ facts, const unsigned char* __restrict__ mask,
              const float* __restrict__ W2, const float* __restrict__ b2,
              const float* __restrict__ W3, const float* __restrict__ b3,
              float* __restrict__ out, float* __restrict__ scoresOut) {
    extern __shared__ float sm[];
    float* sF    = sm + OF_SF;     // [2][32][SFP] transposed facts chunks
    float* sMt   = sm + OF_SMT;    // [128][80]   per-batch effective W1
    float* sH1T  = sm + OF_SH1T;   // [80][SFP]   H1 transposed
    float* sW2t  = sm + OF_SW2;    // [80][40]    W2 transposed [k][h2]
    float* sPart = sm + OF_SPART;  // [10][200]
    float* sq    = sm + OF_SQ;
    float* scb   = sm + OF_SCB;
    float* red   = sm + OF_RED;

    int b = blockIdx.x, tid = threadIdx.x;
    bool active = tid < 500;
    int rt = tid % 50;           // t = rt + 50*i
    int ch = tid / 50;           // 0..9  (tid 500-511 -> ch 10, unused)
    if (ch > 9) ch = 9;

    // -------- prelude --------
    if (tid < FSZ) sq[tid]  = g_q[(size_t)b * FSZ + tid];
    if (tid < H1N) scb[tid] = g_cb[(size_t)b * H1N + tid];
    for (int i = tid; i < H2N * H1N; i += 512) {       // W2t[k][h2] = W2[h2][k]
        int h2 = i / H1N, k = i - h2 * H1N;
        sW2t[k * H2N + h2] = W2[i];
    }
    __syncthreads();

    const float4* factsB = (const float4*)(facts + (size_t)b * TTd * FSZ);

    // chunk 0 global loads + M_b build, then transpose-store chunk 0
    float4 pf[4];
#pragma unroll
    for (int r = 0; r < 4; r++) {
        int i = tid + r * 512;
        if (i < 1600) { int t = i >> 3, j = i & 7; pf[r] = factsB[t * 32 + j]; }
    }
    for (int i = tid; i < FSZ * H1N; i += 512)
        sMt[i] = g_BmT[i] + sq[i / H1N] * g_C2T[i];
#pragma unroll
    for (int r = 0; r < 4; r++) {
        int i = tid + r * 512;
        if (i < 1600) {
            int t = i >> 3, j = i & 7;
            float* p = sF + (j * 4) * SFP + t;
            p[0] = pf[r].x; p[SFP] = pf[r].y; p[2 * SFP] = pf[r].z; p[3 * SFP] = pf[r].w;
        }
    }
    __syncthreads();

    // -------- GEMM1: acc[4 t][4 h-pairs], f32x2, reg-double-buffered --------
    unsigned long long acc[4][4];
#pragma unroll
    for (int i = 0; i < 4; i++)
#pragma unroll
        for (int j = 0; j < 4; j++) acc[i][j] = 0ull;

    const ulonglong2* mrow;
    float fc[4]; ulonglong2 mAc, mBc;

    for (int c = 0; c < NCH; c++) {
        const float* sFb = sF + (c & 1) * (KC * SFP);
        if (c < NCH - 1) {
#pragma unroll
            for (int r = 0; r < 4; r++) {
                int i = tid + r * 512;
                if (i < 1600) { int t = i >> 3, j = i & 7; pf[r] = factsB[t * 32 + (c + 1) * 8 + j]; }
            }
        }
        if (active) {
            // preload row 0 of this chunk
            const float* fb0 = sFb + rt;
#pragma unroll
            for (int i = 0; i < 4; i++) fc[i] = fb0[50 * i];
            mrow = (const ulonglong2*)(sMt + (c * KC) * H1N + ch * 8);
            mAc = mrow[0]; mBc = mrow[1];
#pragma unroll 4
            for (int s = 0; s < KC; s++) {
                float fn[4]; ulonglong2 mAn, mBn;
                if (s < KC - 1) {                    // prefetch next row
                    const float* fb = sFb + (s + 1) * SFP + rt;
#pragma unroll
                    for (int i = 0; i < 4; i++) fn[i] = fb[50 * i];
                    const ulonglong2* mp = (const ulonglong2*)(sMt + (c * KC + s + 1) * H1N + ch * 8);
                    mAn = mp[0]; mBn = mp[1];
                }
#pragma unroll
                for (int i = 0; i < 4; i++) {
                    unsigned long long a_ = dup2(fc[i]);
                    fma2(acc[i][0], a_, mAc.x); fma2(acc[i][1], a_, mAc.y);
                    fma2(acc[i][2], a_, mBc.x); fma2(acc[i][3], a_, mBc.y);
                }
                if (s < KC - 1) {
#pragma unroll
                    for (int i = 0; i < 4; i++) fc[i] = fn[i];
                    mAc = mAn; mBc = mBn;
                }
            }
        }
        if (c < NCH - 1) {
#pragma unroll
            for (int r = 0; r < 4; r++) {
                int i = tid + r * 512;
                if (i < 1600) {
                    int t = i >> 3, j = i & 7;
                    float* p = sF + ((c + 1) & 1) * (KC * SFP) + (j * 4) * SFP + t;
                    p[0] = pf[r].x; p[SFP] = pf[r].y; p[2 * SFP] = pf[r].z; p[3 * SFP] = pf[r].w;
                }
            }
        }
        __syncthreads();
    }

    // epilogue 1: + c_b, sigmoid, store H1 transposed [h][t]
    if (active) {
#pragma unroll
        for (int i = 0; i < 4; i++) {
            int t = rt + 50 * i;
#pragma unroll
            for (int j = 0; j < 4; j++) {
                float2 v = *(float2*)&acc[i][j];
                int h = ch * 8 + 2 * j;
                sH1T[h * SFP + t]       = sigf(v.x + scb[h]);
                sH1T[(h + 1) * SFP + t] = sigf(v.y + scb[h + 1]);
            }
        }
    }
    __syncthreads();

    // -------- GEMM2: acc2[4 t][2 h2-pairs], reg-double-buffered --------
    unsigned long long acc2[4][2];
#pragma unroll
    for (int i = 0; i < 4; i++) { acc2[i][0] = 0ull; acc2[i][1] = 0ull; }
    if (active) {
        float hc[4]; ulonglong2 wc;
        const float* hb0 = sH1T + rt;
#pragma unroll
        for (int i = 0; i < 4; i++) hc[i] = hb0[50 * i];
        wc = *(const ulonglong2*)(sW2t + ch * 4);
#pragma unroll 4
        for (int k = 0; k < H1N; k++) {
            float hn[4]; ulonglong2 wn;
            if (k < H1N - 1) {
                const float* hb = sH1T + (k + 1) * SFP + rt;
#pragma unroll
                for (int i = 0; i < 4; i++) hn[i] = hb[50 * i];
                wn = *(const ulonglong2*)(sW2t + (k + 1) * H2N + ch * 4);
            }
#pragma unroll
            for (int i = 0; i < 4; i++) {
                unsigned long long a_ = dup2(hc[i]);
                fma2(acc2[i][0], a_, wc.x);
                fma2(acc2[i][1], a_, wc.y);
            }
            if (k < H1N - 1) {
#pragma unroll
                for (int i = 0; i < 4; i++) hc[i] = hn[i];
                wc = wn;
            }
        }
        // stage 3 partials: sigmoid(h2)·W3 for this thread's 4 h2-cols
        float b2r[4], w3r[4];
#pragma unroll
        for (int jj = 0; jj < 4; jj++) { b2r[jj] = b2[ch * 4 + jj]; w3r[jj] = W3[ch * 4 + jj]; }
#pragma unroll
        for (int i = 0; i < 4; i++) {
            float2 v0 = *(float2*)&acc2[i][0];
            float2 v1 = *(float2*)&acc2[i][1];
            float part = sigf(v0.x + b2r[0]) * w3r[0]
                       + sigf(v0.y + b2r[1]) * w3r[1]
                       + sigf(v1.x + b2r[2]) * w3r[2]
                       + sigf(v1.y + b2r[3]) * w3r[3];
            sPart[ch * TTd + rt + 50 * i] = part;
        }
    }
    __syncthreads();

    // -------- stage 3 reduce + masked softmax over T=200 (16 warps) --------
    int lane = tid & 31, wid = tid >> 5;
    float sval = 0.f, mpad = -3.402823466e38f;
    if (tid < TTd) {
        float s = b3[0];
#pragma unroll
        for (int c2 = 0; c2 < 10; c2++) s += sPart[c2 * TTd + tid];
        int mv;
        if (g_maskI32) mv = ((const int*)mask)[(size_t)b * TTd + tid];
        else           mv = (int)mask[(size_t)b * TTd + tid];
        if (!mv) s = NEG_BIG_F;
        sval = s; mpad = s;
    }
    float m = mpad;
#pragma unroll
    for (int o = 16; o; o >>= 1) m = fmaxf(m, __shfl_xor_sync(0xffffffffu, m, o));
    if (lane == 0) red[wid] = m;
    __syncthreads();
    if (tid < 32) {
        float mm = (tid < 16) ? red[tid] : -3.402823466e38f;
#pragma unroll
        for (int o = 8; o; o >>= 1) mm = fmaxf(mm, __shfl_xor_sync(0xffffffffu, mm, o));
        if (tid == 0) red[0] = mm;
    }
    __syncthreads();
    float bmax = red[0];
    float p = (tid < TTd) ? __expf(sval - bmax) : 0.f;
    float ssum = p;
#pragma unroll
    for (int o = 16; o; o >>= 1) ssum += __shfl_xor_sync(0xffffffffu, ssum, o);
    __syncthreads();
    if (lane == 0) red[wid] = ssum;
    __syncthreads();
    if (tid < 32) {
        float ss = (tid < 16) ? red[tid] : 0.f;
#pragma unroll
        for (int o = 8; o; o >>= 1) ss += __shfl_xor_sync(0xffffffffu, ss, o);
        if (tid == 0) red[0] = ss;
    }
    __syncthreads();
    float tot = red[0];
    float* sc = sPart;                       // reuse
    if (tid < TTd) {
        float v = p / tot;
        sc[tid] = v;
        scoresOut[(size_t)b * TTd + tid] = v;
    }
    __syncthreads();

    // -------- fused output scaling: out[b,t,:] = facts[b,t,:] * score --------
    float4* out4 = (float4*)(out + (size_t)b * TTd * FSZ);
#pragma unroll 4
    for (int i = tid; i < TTd * (FSZ / 4); i += 512) {
        float s = sc[i >> 5];
        float4 f = factsB[i];
        out4[i] = make_float4(f.x * s, f.y * s, f.z * s, f.w * s);
    }
}

extern "C" void kernel_launch(void* const* d_in, const int* in_sizes, int n_in,
                              void* d_out, int out_size) {
    const float*         query = (const float*)d_in[0];
    const float*         facts = (const float*)d_in[1];
    const unsigned char* maskp = (const unsigned char*)d_in[2];
    const float*         Wq    = (const float*)d_in[3];
    const float*         bq    = (const float*)d_in[4];
    const float*         aP    = (const float*)d_in[5];
    const float*         W1    = (const float*)d_in[6];
    const float*         b1    = (const float*)d_in[7];
    const float*         W2    = (const float*)d_in[8];
    const float*         b2    = (const float*)d_in[9];
    const float*         W3    = (const float*)d_in[10];
    const float*         b3    = (const float*)d_in[11];

    float* out       = (float*)d_out;
    float* scoresOut = out + (size_t)BB * TTd * FSZ;

    cudaFuncSetAttribute(k_scores, cudaFuncAttributeMaxDynamicSharedMemorySize,
                         SMEM_FLOATS * 4);

    k_detect<<<1, 256>>>(maskp);
    k_prep <<<64, 256>>>(W1, Wq);
    k_query<<<BB, 128>>>(query, bq, aP, b1);
    k_scores<<<BB, 512, SMEM_FLOATS * 4>>>(facts, maskp, W2, b2, W3, b3, out, scoresOut);
}

// round 8
// speedup vs baseline: 1.0609x; 1.0018x over previous
#include <cuda_runtime.h>
#include <cstdint>

#define BB   2048
#define TTd  200
#define FSZ  128
#define H1N  80
#define H2N  40
#define KC   32
#define NCH  4
#define SFP  205            // t-stride: conflict-free transpose stores & strided loads
#define NEG_BIG_F (-4294967295.0f)

// ---- shared memory float offsets for k_scores ----
#define OF_SF    0                       // 2*32*205 = 13120
#define OF_SMT   13120                   // 128*80   = 10240
#define OF_SH1T  23360                   // 80*205   = 16400 (H1 transposed [k][t])
#define OF_SW2   39760                   // 80*40    = 3200  ([k][h2])
#define OF_SPART 42960                   // 10*200   = 2000
#define OF_SQ    44960                   // 128
#define OF_SCB   45088                   // 80
#define OF_RED   45168                   // 32
#define SMEM_FLOATS 45200                // *4 = 180,800 bytes

// ---- device scratch (static, no runtime allocation) ----
__device__ float g_q  [BB * FSZ];
__device__ float g_cb [BB * H1N];
__device__ float g_AT [FSZ * H1N];
__device__ float g_BmT[FSZ * H1N];
__device__ float g_C2T[FSZ * H1N];
__device__ float g_WqT[FSZ * FSZ];
__device__ int   g_maskI32;

// packed fp32x2 helpers (Blackwell paired FP32 — 2x scalar FFMA throughput)
__device__ __forceinline__ void fma2(unsigned long long &d,
                                     unsigned long long a,
                                     unsigned long long b) {
    asm("fma.rn.f32x2 %0, %1, %2, %0;" : "+l"(d) : "l"(a), "l"(b));
}
__device__ __forceinline__ unsigned long long dup2(float x) {
    unsigned long long r;
    asm("mov.b64 %0, {%1, %1};" : "=l"(r) : "f"(x));
    return r;
}
__device__ __forceinline__ float sigf(float x) {
    return 1.0f / (1.0f + __expf(-x));
}

// ============================================================
// Kernel 0: mask dtype probe (JAX bool as int32 vs byte mask).
// ============================================================
__global__ void k_detect(const unsigned char* __restrict__ m) {
    __shared__ int bad;
    if (threadIdx.x == 0) bad = 0;
    __syncthreads();
    int acc = 0;
    for (int i = threadIdx.x; i < 4096; i += blockDim.x)
        if ((i & 3) && m[i]) acc = 1;
    if (acc) atomicOr(&bad, 1);
    __syncthreads();
    if (threadIdx.x == 0) g_maskI32 = bad ? 0 : 1;
}

// ============================================================
// Kernel 1: weight preprocessing (DIN concat factorization).
// ============================================================
__global__ void k_prep(const float* __restrict__ W1, const float* __restrict__ Wq) {
    int idx = blockIdx.x * blockDim.x + threadIdx.x;
    if (idx < FSZ * H1N) {
        int d = idx / H1N, h = idx - d * H1N;
        const float* r = W1 + (size_t)h * 4 * FSZ;
        float w0 = r[d], w1 = r[FSZ + d], w2 = r[2 * FSZ + d], w3v = r[3 * FSZ + d];
        g_AT[idx]  = w0 + w2;
        g_BmT[idx] = w1 - w2;
        g_C2T[idx] = w3v;
    }
    if (idx < FSZ * FSZ) {
        int k = idx / FSZ, d = idx - k * FSZ;
        g_WqT[idx] = Wq[d * FSZ + k];
    }
}

// ============================================================
// Kernel 2: q = PReLU(query @ Wq^T + bq), c_b = q @ A^T + b1
// ============================================================
__global__ void k_query(const float* __restrict__ query, const float* __restrict__ bq,
                        const float* __restrict__ aP, const float* __restrict__ b1) {
    __shared__ float sqr[FSZ];
    __shared__ float sqv[FSZ];
    int b = blockIdx.x, tid = threadIdx.x;
    sqr[tid] = query[(size_t)b * FSZ + tid];
    __syncthreads();
    float acc = 0.f;
#pragma unroll 8
    for (int k = 0; k < FSZ; k++) acc += sqr[k] * g_WqT[k * FSZ + tid];
    acc += bq[tid];
    float a = aP[0];
    float q = acc > 0.f ? acc : a * acc;
    g_q[(size_t)b * FSZ + tid] = q;
    sqv[tid] = q;
    __syncthreads();
    if (tid < H1N) {
        float c = 0.f;
#pragma unroll 8
        for (int d = 0; d < FSZ; d++) c += sqv[d] * g_AT[d * H1N + tid];
        g_cb[(size_t)b * H1N + tid] = c + b1[tid];
    }
}

// ============================================================
// Kernel 3: one CTA per batch, 512 threads (500 active in GEMM).
//   rt = tid%50 -> t = rt + 50*i (i<4, lane-contiguous loads)
//   ch = tid/50 -> h-cols ch*8 (near-warp-uniform m loads)
// Manual register double-buffering in both GEMM mainloops to kill
// LDS->FFMA RAW stalls (R6 was scoreboard-stall bound: issue 34%).
// GEMM1 -> sigmoid -> H1T[k][t] -> GEMM2 -> sigmoid + W3 dot
// -> masked softmax -> fused facts*score.
// ============================================================
__global__ __launch_bounds__(512, 1)
void k_scores(const float* __restrict__ facts, const unsigned char* __restrict__ mask,
              const float* __restrict__ W2, const float* __restrict__ b2,
              const float* __restrict__ W3, const float* __restrict__ b3,
              float* __restrict__ out, float* __restrict__ scoresOut) {
    extern __shared__ float sm[];
    float* sF    = sm + OF_SF;     // [2][32][SFP] transposed facts chunks
    float* sMt   = sm + OF_SMT;    // [128][80]   per-batch effective W1
    float* sH1T  = sm + OF_SH1T;   // [80][SFP]   H1 transposed
    float* sW2t  = sm + OF_SW2;    // [80][40]    W2 transposed [k][h2]
    float* sPart = sm + OF_SPART;  // [10][200]
    float* sq    = sm + OF_SQ;
    float* scb   = sm + OF_SCB;
    float* red   = sm + OF_RED;

    int b = blockIdx.x, tid = threadIdx.x;
    bool active = tid < 500;
    int rt = tid % 50;           // t = rt + 50*i
    int ch = tid / 50;           // 0..9  (tid 500-511 -> ch 10, unused)
    if (ch > 9) ch = 9;

    // -------- prelude --------
    if (tid < FSZ) sq[tid]  = g_q[(size_t)b * FSZ + tid];
    if (tid < H1N) scb[tid] = g_cb[(size_t)b * H1N + tid];
    for (int i = tid; i < H2N * H1N; i += 512) {       // W2t[k][h2] = W2[h2][k]
        int h2 = i / H1N, k = i - h2 * H1N;
        sW2t[k * H2N + h2] = W2[i];
    }
    __syncthreads();

    const float4* factsB = (const float4*)(facts + (size_t)b * TTd * FSZ);

    // chunk 0 global loads + M_b build, then transpose-store chunk 0
    float4 pf[4];
#pragma unroll
    for (int r = 0; r < 4; r++) {
        int i = tid + r * 512;
        if (i < 1600) { int t = i >> 3, j = i & 7; pf[r] = factsB[t * 32 + j]; }
    }
    for (int i = tid; i < FSZ * H1N; i += 512)
        sMt[i] = g_BmT[i] + sq[i / H1N] * g_C2T[i];
#pragma unroll
    for (int r = 0; r < 4; r++) {
        int i = tid + r * 512;
        if (i < 1600) {
            int t = i >> 3, j = i & 7;
            float* p = sF + (j * 4) * SFP + t;
            p[0] = pf[r].x; p[SFP] = pf[r].y; p[2 * SFP] = pf[r].z; p[3 * SFP] = pf[r].w;
        }
    }
    __syncthreads();

    // -------- GEMM1: acc[4 t][4 h-pairs], f32x2, reg-double-buffered --------
    unsigned long long acc[4][4];
#pragma unroll
    for (int i = 0; i < 4; i++)
#pragma unroll
        for (int j = 0; j < 4; j++) acc[i][j] = 0ull;

    const ulonglong2* mrow;
    float fc[4]; ulonglong2 mAc, mBc;

    for (int c = 0; c < NCH; c++) {
        const float* sFb = sF + (c & 1) * (KC * SFP);
        if (c < NCH - 1) {
#pragma unroll
            for (int r = 0; r < 4; r++) {
                int i = tid + r * 512;
                if (i < 1600) { int t = i >> 3, j = i & 7; pf[r] = factsB[t * 32 + (c + 1) * 8 + j]; }
            }
        }
        if (active) {
            // preload row 0 of this chunk
            const float* fb0 = sFb + rt;
#pragma unroll
            for (int i = 0; i < 4; i++) fc[i] = fb0[50 * i];
            mrow = (const ulonglong2*)(sMt + (c * KC) * H1N + ch * 8);
            mAc = mrow[0]; mBc = mrow[1];
#pragma unroll 4
            for (int s = 0; s < KC; s++) {
                float fn[4]; ulonglong2 mAn, mBn;
                if (s < KC - 1) {                    // prefetch next row
                    const float* fb = sFb + (s + 1) * SFP + rt;
#pragma unroll
                    for (int i = 0; i < 4; i++) fn[i] = fb[50 * i];
                    const ulonglong2* mp = (const ulonglong2*)(sMt + (c * KC + s + 1) * H1N + ch * 8);
                    mAn = mp[0]; mBn = mp[1];
                }
#pragma unroll
                for (int i = 0; i < 4; i++) {
                    unsigned long long a_ = dup2(fc[i]);
                    fma2(acc[i][0], a_, mAc.x); fma2(acc[i][1], a_, mAc.y);
                    fma2(acc[i][2], a_, mBc.x); fma2(acc[i][3], a_, mBc.y);
                }
                if (s < KC - 1) {
#pragma unroll
                    for (int i = 0; i < 4; i++) fc[i] = fn[i];
                    mAc = mAn; mBc = mBn;
                }
            }
        }
        if (c < NCH - 1) {
#pragma unroll
            for (int r = 0; r < 4; r++) {
                int i = tid + r * 512;
                if (i < 1600) {
                    int t = i >> 3, j = i & 7;
                    float* p = sF + ((c + 1) & 1) * (KC * SFP) + (j * 4) * SFP + t;
                    p[0] = pf[r].x; p[SFP] = pf[r].y; p[2 * SFP] = pf[r].z; p[3 * SFP] = pf[r].w;
                }
            }
        }
        __syncthreads();
    }

    // epilogue 1: + c_b, sigmoid, store H1 transposed [h][t]
    if (active) {
#pragma unroll
        for (int i = 0; i < 4; i++) {
            int t = rt + 50 * i;
#pragma unroll
            for (int j = 0; j < 4; j++) {
                float2 v = *(float2*)&acc[i][j];
                int h = ch * 8 + 2 * j;
                sH1T[h * SFP + t]       = sigf(v.x + scb[h]);
                sH1T[(h + 1) * SFP + t] = sigf(v.y + scb[h + 1]);
            }
        }
    }
    __syncthreads();

    // -------- GEMM2: acc2[4 t][2 h2-pairs], reg-double-buffered --------
    unsigned long long acc2[4][2];
#pragma unroll
    for (int i = 0; i < 4; i++) { acc2[i][0] = 0ull; acc2[i][1] = 0ull; }
    if (active) {
        float hc[4]; ulonglong2 wc;
        const float* hb0 = sH1T + rt;
#pragma unroll
        for (int i = 0; i < 4; i++) hc[i] = hb0[50 * i];
        wc = *(const ulonglong2*)(sW2t + ch * 4);
#pragma unroll 4
        for (int k = 0; k < H1N; k++) {
            float hn[4]; ulonglong2 wn;
            if (k < H1N - 1) {
                const float* hb = sH1T + (k + 1) * SFP + rt;
#pragma unroll
                for (int i = 0; i < 4; i++) hn[i] = hb[50 * i];
                wn = *(const ulonglong2*)(sW2t + (k + 1) * H2N + ch * 4);
            }
#pragma unroll
            for (int i = 0; i < 4; i++) {
                unsigned long long a_ = dup2(hc[i]);
                fma2(acc2[i][0], a_, wc.x);
                fma2(acc2[i][1], a_, wc.y);
            }
            if (k < H1N - 1) {
#pragma unroll
                for (int i = 0; i < 4; i++) hc[i] = hn[i];
                wc = wn;
            }
        }
        // stage 3 partials: sigmoid(h2)·W3 for this thread's 4 h2-cols
        float b2r[4], w3r[4];
#pragma unroll
        for (int jj = 0; jj < 4; jj++) { b2r[jj] = b2[ch * 4 + jj]; w3r[jj] = W3[ch * 4 + jj]; }
#pragma unroll
        for (int i = 0; i < 4; i++) {
            float2 v0 = *(float2*)&acc2[i][0];
            float2 v1 = *(float2*)&acc2[i][1];
            float part = sigf(v0.x + b2r[0]) * w3r[0]
                       + sigf(v0.y + b2r[1]) * w3r[1]
                       + sigf(v1.x + b2r[2]) * w3r[2]
                       + sigf(v1.y + b2r[3]) * w3r[3];
            sPart[ch * TTd + rt + 50 * i] = part;
        }
    }
    __syncthreads();

    // -------- stage 3 reduce + masked softmax over T=200 (16 warps) --------
    int lane = tid & 31, wid = tid >> 5;
    float sval = 0.f, mpad = -3.402823466e38f;
    if (tid < TTd) {
        float s = b3[0];
#pragma unroll
        for (int c2 = 0; c2 < 10; c2++) s += sPart[c2 * TTd + tid];
        int mv;
        if (g_maskI32) mv = ((const int*)mask)[(size_t)b * TTd + tid];
        else           mv = (int)mask[(size_t)b * TTd + tid];
        if (!mv) s = NEG_BIG_F;
        sval = s; mpad = s;
    }
    float m = mpad;
#pragma unroll
    for (int o = 16; o; o >>= 1) m = fmaxf(m, __shfl_xor_sync(0xffffffffu, m, o));
    if (lane == 0) red[wid] = m;
    __syncthreads();
    if (tid < 32) {
        float mm = (tid < 16) ? red[tid] : -3.402823466e38f;
#pragma unroll
        for (int o = 8; o; o >>= 1) mm = fmaxf(mm, __shfl_xor_sync(0xffffffffu, mm, o));
        if (tid == 0) red[0] = mm;
    }
    __syncthreads();
    float bmax = red[0];
    float p = (tid < TTd) ? __expf(sval - bmax) : 0.f;
    float ssum = p;
#pragma unroll
    for (int o = 16; o; o >>= 1) ssum += __shfl_xor_sync(0xffffffffu, ssum, o);
    __syncthreads();
    if (lane == 0) red[wid] = ssum;
    __syncthreads();
    if (tid < 32) {
        float ss = (tid < 16) ? red[tid] : 0.f;
#pragma unroll
        for (int o = 8; o; o >>= 1) ss += __shfl_xor_sync(0xffffffffu, ss, o);
        if (tid == 0) red[0] = ss;
    }
    __syncthreads();
    float tot = red[0];
    float* sc = sPart;                       // reuse
    if (tid < TTd) {
        float v = p / tot;
        sc[tid] = v;
        scoresOut[(size_t)b * TTd + tid] = v;
    }
    __syncthreads();

    // -------- fused output scaling: out[b,t,:] = facts[b,t,:] * score --------
    float4* out4 = (float4*)(out + (size_t)b * TTd * FSZ);
#pragma unroll 4
    for (int i = tid; i < TTd * (FSZ / 4); i += 512) {
        float s = sc[i >> 5];
        float4 f = factsB[i];
        out4[i] = make_float4(f.x * s, f.y * s, f.z * s, f.w * s);
    }
}

extern "C" void kernel_launch(void* const* d_in, const int* in_sizes, int n_in,
                              void* d_out, int out_size) {
    const float*         query = (const float*)d_in[0];
    const float*         facts = (const float*)d_in[1];
    const unsigned char* maskp = (const unsigned char*)d_in[2];
    const float*         Wq    = (const float*)d_in[3];
    const float*         bq    = (const float*)d_in[4];
    const float*         aP    = (const float*)d_in[5];
    const float*         W1    = (const float*)d_in[6];
    const float*         b1    = (const float*)d_in[7];
    const float*         W2    = (const float*)d_in[8];
    const float*         b2    = (const float*)d_in[9];
    const float*         W3    = (const float*)d_in[10];
    const float*         b3    = (const float*)d_in[11];

    float* out       = (float*)d_out;
    float* scoresOut = out + (size_t)BB * TTd * FSZ;

    cudaFuncSetAttribute(k_scores, cudaFuncAttributeMaxDynamicSharedMemorySize,
                         SMEM_FLOATS * 4);

    k_detect<<<1, 256>>>(maskp);
    k_prep <<<64, 256>>>(W1, Wq);
    k_query<<<BB, 128>>>(query, bq, aP, b1);
    k_scores<<<BB, 512, SMEM_FLOATS * 4>>>(facts, maskp, W2, b2, W3, b3, out, scoresOut);
}